// round 4
// baseline (speedup 1.0000x reference)
#include <cuda_runtime.h>
#include <math.h>

// Problem constants
#define Bb 2
#define Cc 64
#define Nn 8192
#define Oo 64
#define Kk 20
#define NPOINTS (Bb * Nn)            // 16384
#define MROWS   (NPOINTS * Kk)       // 327680
#define NBLK_CONV (MROWS / 160)      // 2048

// ---------------- scratch (device globals; allocation-free) ----------------
__device__ float  g_ndist[134217728];   // [B][N][N]  536 MB
__device__ float  g_xt[NPOINTS * Cc];   // [B*N][C]   transposed points
__device__ float  g_sq[NPOINTS];        // ||x||^2 per point
__device__ int    g_idx[MROWS];         // top-K indices, [B*N][K]
__device__ float  g_u[NPOINTS * Oo];    // center term (W2-W1)·cen
__device__ double g_sum[Oo];
__device__ double g_sumsq[Oo];
__device__ float  g_sc[Oo];
__device__ float  g_sh[Oo];

// monotonic float <-> sortable uint mapping
__device__ __forceinline__ unsigned f2key(float f) {
    unsigned u = __float_as_uint(f);
    return (u & 0x80000000u) ? ~u : (u | 0x80000000u);
}
__device__ __forceinline__ float key2f(unsigned m) {
    return __uint_as_float((m & 0x80000000u) ? (m & 0x7FFFFFFFu) : ~m);
}

// ---------------- kernel 0: zero accumulators ----------------
__global__ void k_zero() {
    int t = threadIdx.x;
    if (t < Oo) { g_sum[t] = 0.0; g_sumsq[t] = 0.0; }
}

// ---------------- kernel 1: transpose x -> xt, compute sq ----------------
__global__ void k_prep(const float* __restrict__ x) {
    int p = blockIdx.x * 256 + threadIdx.x;   // 0..16383
    int b = p >> 13;
    int n = p & (Nn - 1);
    const float* xb = x + (size_t)b * Cc * Nn;
    float s = 0.f;
    #pragma unroll
    for (int c = 0; c < Cc; c++) {
        float v = xb[c * Nn + n];
        s += v * v;
        g_xt[(size_t)p * Cc + c] = v;
    }
    g_sq[p] = s;
}

// ---------------- kernel 2: neg-dist GEMM  d = 2*x_i.x_j - |x_i|^2 - |x_j|^2
#define DSTRIDE 132
__global__ void k_dist(const float* __restrict__ x) {
    extern __shared__ float sm[];
    float* As = sm;
    float* Bs = sm + 64 * DSTRIDE;
    const int b  = blockIdx.z;
    const int i0 = blockIdx.y * 128;
    const int j0 = blockIdx.x * 128;
    const int tid = threadIdx.x;
    const float* xb = x + (size_t)b * Cc * Nn;

    for (int L = tid; L < 2048; L += 256) {
        int c = L >> 5, q = L & 31;
        float4 v = *(const float4*)(xb + c * Nn + i0 + q * 4);
        *(float4*)(As + c * DSTRIDE + q * 4) = v;
        float4 w = *(const float4*)(xb + c * Nn + j0 + q * 4);
        *(float4*)(Bs + c * DSTRIDE + q * 4) = w;
    }
    __syncthreads();

    int tx = tid & 15, ty = tid >> 4;
    float acc[8][8];
    #pragma unroll
    for (int i = 0; i < 8; i++)
        #pragma unroll
        for (int j = 0; j < 8; j++) acc[i][j] = 0.f;

    #pragma unroll 4
    for (int kk = 0; kk < 64; kk++) {
        float4 a0 = *(float4*)(As + kk * DSTRIDE + ty * 8);
        float4 a1 = *(float4*)(As + kk * DSTRIDE + ty * 8 + 4);
        float4 b0 = *(float4*)(Bs + kk * DSTRIDE + tx * 8);
        float4 b1 = *(float4*)(Bs + kk * DSTRIDE + tx * 8 + 4);
        float a[8] = {a0.x, a0.y, a0.z, a0.w, a1.x, a1.y, a1.z, a1.w};
        float bbv[8] = {b0.x, b0.y, b0.z, b0.w, b1.x, b1.y, b1.z, b1.w};
        #pragma unroll
        for (int i = 0; i < 8; i++)
            #pragma unroll
            for (int j = 0; j < 8; j++) acc[i][j] += a[i] * bbv[j];
    }

    float sqj[8];
    #pragma unroll
    for (int j = 0; j < 8; j++) sqj[j] = g_sq[b * Nn + j0 + tx * 8 + j];
    #pragma unroll
    for (int i = 0; i < 8; i++) {
        float sqi = g_sq[b * Nn + i0 + ty * 8 + i];
        float* dst = g_ndist + ((size_t)(b * Nn + i0 + ty * 8 + i)) * Nn + j0 + tx * 8;
        float4 r0, r1;
        r0.x = 2.f * acc[i][0] - sqi - sqj[0];
        r0.y = 2.f * acc[i][1] - sqi - sqj[1];
        r0.z = 2.f * acc[i][2] - sqi - sqj[2];
        r0.w = 2.f * acc[i][3] - sqi - sqj[3];
        r1.x = 2.f * acc[i][4] - sqi - sqj[4];
        r1.y = 2.f * acc[i][5] - sqi - sqj[5];
        r1.z = 2.f * acc[i][6] - sqi - sqj[6];
        r1.w = 2.f * acc[i][7] - sqi - sqj[7];
        *(float4*)dst = r0;
        *(float4*)(dst + 4) = r1;
    }
}

// ---------------- kernel 3: top-K set select, register-resident ------------
// Row lives in registers (32 vals/thread). Sampled threshold (12th of 256),
// survivors (~382 expected) compacted to a small smem (val,idx) buffer,
// warp 0 extracts top-20. Exact global-memory fallback if under/overflow
// (probability ~1e-13). Tie-break = lowest index (matches jax top_k).
#define TCAP 1536
__global__ __launch_bounds__(256) void k_topk() {
    __shared__ float compv[TCAP];
    __shared__ int   compi[TCAP];
    __shared__ float samp[256];
    __shared__ float s_thr;
    __shared__ int   s_n;
    __shared__ int   chosen[Kk];

    int row  = blockIdx.x;
    int tid  = threadIdx.x;
    int lane = tid & 31;
    int warp = tid >> 5;
    const float*  srcf = g_ndist + (size_t)row * Nn;
    const float4* src  = (const float4*)srcf;

    // 32 row values per thread, 8 independent LDG.128 (MLP=8)
    float4 v[8];
    #pragma unroll
    for (int s = 0; s < 8; s++) v[s] = src[tid + s * 256];

    if (tid == 0) s_n = 0;
    // spread sample positions without dynamic register indexing
    float smp = v[0].x;
    #pragma unroll
    for (int s = 1; s < 8; s++) if ((tid & 7) == s) smp = v[s].x;
    samp[tid] = smp;
    __syncthreads();

    // warp 0: threshold = 12th largest of 256 samples
    if (warp == 0) {
        float lv[8];
        #pragma unroll
        for (int s = 0; s < 8; s++) lv[s] = samp[lane + 32 * s];
        for (int k = 0; ; k++) {
            float lmax = lv[0];
            #pragma unroll
            for (int s = 1; s < 8; s++) lmax = fmaxf(lmax, lv[s]);
            unsigned key = f2key(lmax);
            unsigned m = __reduce_max_sync(0xffffffffu, key);
            if (k == 11) { if (lane == 0) s_thr = key2f(m); break; }
            int win = __ffs(__ballot_sync(0xffffffffu, key == m)) - 1;
            if (lane == win) {
                bool done = false;
                #pragma unroll
                for (int s = 0; s < 8; s++)
                    if (!done && lv[s] == lmax) { lv[s] = -INFINITY; done = true; }
            }
        }
    }
    __syncthreads();
    float thr = s_thr;

    // compact survivors straight from registers
    #pragma unroll
    for (int s = 0; s < 8; s++) {
        int j = (tid + s * 256) * 4;
        float4 w = v[s];
        if (w.x > thr) { int p = atomicAdd(&s_n, 1); if (p < TCAP) { compv[p] = w.x; compi[p] = j;     } }
        if (w.y > thr) { int p = atomicAdd(&s_n, 1); if (p < TCAP) { compv[p] = w.y; compi[p] = j + 1; } }
        if (w.z > thr) { int p = atomicAdd(&s_n, 1); if (p < TCAP) { compv[p] = w.z; compi[p] = j + 2; } }
        if (w.w > thr) { int p = atomicAdd(&s_n, 1); if (p < TCAP) { compv[p] = w.w; compi[p] = j + 3; } }
    }
    __syncthreads();
    int n = s_n;

    if (n >= Kk && n <= TCAP) {
        if (warp == 0) {
            int nseg = (n + 31) >> 5;
            float bv = -INFINITY; int bs = -1;
            for (int s = 0; s < nseg; s++) {
                int c = lane + (s << 5);
                if (c < n && compv[c] > bv) { bv = compv[c]; bs = c; }
            }
            for (int k = 0; k < Kk; k++) {
                unsigned key = f2key(bv);
                unsigned m = __reduce_max_sync(0xffffffffu, key);
                int cand = (key == m && bs >= 0) ? compi[bs] : 0x7fffffff;
                int widx = __reduce_min_sync(0xffffffffu, cand);
                if (lane == 0) g_idx[row * Kk + k] = widx;
                if (cand == widx) {
                    compv[bs] = -INFINITY;
                    bv = -INFINITY; bs = -1;
                    for (int s = 0; s < nseg; s++) {
                        int c = lane + (s << 5);
                        if (c < n && compv[c] > bv) { bv = compv[c]; bs = c; }
                    }
                }
            }
        }
    } else if (warp == 0) {
        // exact fallback: 20 passes over the global row (never runs in practice)
        for (int k = 0; k < Kk; k++) {
            float bv = -INFINITY; int bi = 0x7fffffff;
            for (int j = lane; j < Nn; j += 32) {
                bool skip = false;
                for (int q = 0; q < k; q++) if (chosen[q] == j) skip = true;
                float val = srcf[j];
                if (!skip && val > bv) { bv = val; bi = j; }
            }
            unsigned key = f2key(bv);
            unsigned m = __reduce_max_sync(0xffffffffu, key);
            int cand = (key == m) ? bi : 0x7fffffff;
            int widx = __reduce_min_sync(0xffffffffu, cand);
            if (lane == 0) { g_idx[row * Kk + k] = widx; chosen[k] = widx; }
            __syncwarp();
        }
    }
}

// ---------------- kernel 4: center term u = (W[:,C:]-W[:,:C]) . cen -------
__global__ void k_u(const float* __restrict__ W) {
    __shared__ float Wd[64 * 65];   // [c][o], stride 65 (conflict-free)
    __shared__ float cs[4 * 64];
    int tid = threadIdx.x;
    for (int L = tid; L < 4096; L += 256) {
        int c = L & 63, o = L >> 6;
        Wd[c * 65 + o] = W[o * 128 + 64 + c] - W[o * 128 + c];
    }
    int p0 = blockIdx.x * 4;
    {
        int pi = tid >> 6, c = tid & 63;
        cs[pi * 64 + c] = g_xt[(size_t)(p0 + pi) * 64 + c];
    }
    __syncthreads();
    int o = tid & 63, pi = tid >> 6;
    float a = 0.f;
    #pragma unroll
    for (int c = 0; c < 64; c++) a += Wd[c * 65 + o] * cs[pi * 64 + c];
    g_u[(size_t)(p0 + pi) * 64 + o] = a;
}

// ---------------- kernel 5/7: gathered GEMM  h = A·nbr + u ----------------
#define SA 161
#define WS_OFF 10400   // floats (41600 B region for As/hbuf)
template<int MODE>
__global__ void k_conv(const float* __restrict__ W, float* __restrict__ out) {
    extern __shared__ float sm[];
    float* As = sm;            // [64][161]  (MODE1: reused as hbuf [160][65])
    float* Ws = sm + WS_OFF;   // [64][68]
    __shared__ int   rowb[160];
    __shared__ int   ub[160];
    __shared__ float ssum[64];
    __shared__ float ssq[64];
    __shared__ float ssc[64];
    __shared__ float ssh[64];

    int tid = threadIdx.x;
    int m0 = blockIdx.x * 160;

    if (tid < 160) {
        int m = m0 + tid;
        int nb = g_idx[m];
        int pt = m / Kk;           // global point index b*N+n
        int b  = pt >> 13;
        rowb[tid] = b * Nn + nb;   // gathered xt row
        ub[tid]   = pt;            // u row
    }
    for (int L = tid; L < 4096; L += 256) {
        int c = L & 63, o = L >> 6;
        Ws[c * 68 + o] = W[o * 128 + c];   // A part, K-major
    }
    if (MODE == 0) { if (tid < 64) { ssum[tid] = 0.f; ssq[tid] = 0.f; } }
    else           { if (tid < 64) { ssc[tid] = g_sc[tid]; ssh[tid] = g_sh[tid]; } }
    __syncthreads();

    for (int L = tid; L < 2560; L += 256) {
        int r = L >> 4, c4 = L & 15;
        float4 v = *(const float4*)(g_xt + (size_t)rowb[r] * 64 + c4 * 4);
        As[(c4 * 4 + 0) * SA + r] = v.x;
        As[(c4 * 4 + 1) * SA + r] = v.y;
        As[(c4 * 4 + 2) * SA + r] = v.z;
        As[(c4 * 4 + 3) * SA + r] = v.w;
    }
    __syncthreads();

    int tx = tid & 7, ty = tid >> 3;   // tx: 8 col-groups, ty: 32 row-groups
    float acc[5][8];
    #pragma unroll
    for (int i = 0; i < 5; i++)
        #pragma unroll
        for (int j = 0; j < 8; j++) acc[i][j] = 0.f;

    #pragma unroll 4
    for (int kk = 0; kk < 64; kk++) {
        float a[5];
        #pragma unroll
        for (int i = 0; i < 5; i++) a[i] = As[kk * SA + ty * 5 + i];
        float4 b0 = *(float4*)(Ws + kk * 68 + tx * 8);
        float4 b1 = *(float4*)(Ws + kk * 68 + tx * 8 + 4);
        float bbv[8] = {b0.x, b0.y, b0.z, b0.w, b1.x, b1.y, b1.z, b1.w};
        #pragma unroll
        for (int i = 0; i < 5; i++)
            #pragma unroll
            for (int j = 0; j < 8; j++) acc[i][j] += a[i] * bbv[j];
    }

    // add center term
    float hv[5][8];
    #pragma unroll
    for (int i = 0; i < 5; i++) {
        const float* up = g_u + (size_t)ub[ty * 5 + i] * 64 + tx * 8;
        float4 u0 = *(const float4*)up;
        float4 u1 = *(const float4*)(up + 4);
        float uv[8] = {u0.x, u0.y, u0.z, u0.w, u1.x, u1.y, u1.z, u1.w};
        #pragma unroll
        for (int j = 0; j < 8; j++) hv[i][j] = acc[i][j] + uv[j];
    }

    if (MODE == 0) {
        float ps[8], pq[8];
        #pragma unroll
        for (int j = 0; j < 8; j++) { ps[j] = 0.f; pq[j] = 0.f; }
        #pragma unroll
        for (int i = 0; i < 5; i++)
            #pragma unroll
            for (int j = 0; j < 8; j++) {
                float v = hv[i][j];
                ps[j] += v; pq[j] += v * v;
            }
        #pragma unroll
        for (int j = 0; j < 8; j++) {
            atomicAdd(&ssum[tx * 8 + j], ps[j]);
            atomicAdd(&ssq [tx * 8 + j], pq[j]);
        }
        __syncthreads();
        if (tid < 64) {
            atomicAdd(&g_sum[tid],   (double)ssum[tid]);
            atomicAdd(&g_sumsq[tid], (double)ssq[tid]);
        }
    } else {
        __syncthreads();  // As fully consumed; safe to reuse as hbuf
        #pragma unroll
        for (int i = 0; i < 5; i++)
            #pragma unroll
            for (int j = 0; j < 8; j++) {
                int o = tx * 8 + j;
                float v = hv[i][j] * ssc[o] + ssh[o];
                v = (v >= 0.f) ? v : 0.2f * v;
                As[(ty * 5 + i) * 65 + o] = v;
            }
        __syncthreads();
        for (int task = tid; task < 512; task += 256) {
            int p = task >> 6, o = task & 63;
            float mx = -INFINITY;
            #pragma unroll
            for (int k = 0; k < Kk; k++)
                mx = fmaxf(mx, As[(p * Kk + k) * 65 + o]);
            int pt = m0 / Kk + p;
            int b = pt >> 13, n = pt & (Nn - 1);
            out[((size_t)b * 64 + o) * Nn + n] = mx;
        }
    }
}

// ---------------- kernel 6: finalize BN scale/shift ----------------
__global__ void k_fin(const float* __restrict__ gamma, const float* __restrict__ beta) {
    int o = threadIdx.x;
    if (o < Oo) {
        double cnt  = (double)MROWS;
        double mean = g_sum[o] / cnt;
        double var  = g_sumsq[o] / cnt - mean * mean;
        float inv = rsqrtf((float)(var + 1e-5));
        float sc  = gamma[o] * inv;
        g_sc[o] = sc;
        g_sh[o] = beta[o] - (float)mean * sc;
    }
}

// ---------------- launcher ----------------
extern "C" void kernel_launch(void* const* d_in, const int* in_sizes, int n_in,
                              void* d_out, int out_size) {
    const float* x     = (const float*)d_in[0];
    const float* W     = (const float*)d_in[1];
    const float* gamma = (const float*)d_in[2];
    const float* beta  = (const float*)d_in[3];
    float* out = (float*)d_out;

    const int SMEM_DIST = 2 * 64 * DSTRIDE * sizeof(float);          // 67584
    const int SMEM_CONV = (WS_OFF + 64 * 68) * sizeof(float);        // 59008

    cudaFuncSetAttribute(k_dist,    cudaFuncAttributeMaxDynamicSharedMemorySize, SMEM_DIST);
    cudaFuncSetAttribute(k_conv<0>, cudaFuncAttributeMaxDynamicSharedMemorySize, SMEM_CONV);
    cudaFuncSetAttribute(k_conv<1>, cudaFuncAttributeMaxDynamicSharedMemorySize, SMEM_CONV);

    k_zero<<<1, 64>>>();
    k_prep<<<NPOINTS / 256, 256>>>(x);
    k_dist<<<dim3(Nn / 128, Nn / 128, Bb), 256, SMEM_DIST>>>(x);
    k_topk<<<NPOINTS, 256>>>();
    k_u<<<NPOINTS / 4, 256>>>(W);
    k_conv<0><<<NBLK_CONV, 256, SMEM_CONV>>>(W, out);
    k_fin<<<1, 64>>>(gamma, beta);
    k_conv<1><<<NBLK_CONV, 256, SMEM_CONV>>>(W, out);
}

// round 6
// speedup vs baseline: 1.0261x; 1.0261x over previous
#include <cuda_runtime.h>
#include <math.h>

// Problem constants
#define Bb 2
#define Cc 64
#define Nn 8192
#define Oo 64
#define Kk 20
#define NPOINTS (Bb * Nn)            // 16384
#define MROWS   (NPOINTS * Kk)       // 327680
#define NBLK_CONV (MROWS / 160)      // 2048

// ---------------- scratch (device globals; allocation-free) ----------------
__device__ float  g_ndist[134217728];   // [B][N][N]  536 MB
__device__ float  g_xt[NPOINTS * Cc];   // [B*N][C]   transposed points
__device__ float  g_sq[NPOINTS];        // ||x||^2 per point
__device__ int    g_idx[MROWS];         // top-K indices, [B*N][K]
__device__ float  g_u[NPOINTS * Oo];    // center term (W2-W1)·cen
__device__ double g_sum[Oo];
__device__ double g_sumsq[Oo];
__device__ float  g_sc[Oo];
__device__ float  g_sh[Oo];

// monotonic float <-> sortable uint mapping
__device__ __forceinline__ unsigned f2key(float f) {
    unsigned u = __float_as_uint(f);
    return (u & 0x80000000u) ? ~u : (u | 0x80000000u);
}
__device__ __forceinline__ float key2f(unsigned m) {
    return __uint_as_float((m & 0x80000000u) ? (m & 0x7FFFFFFFu) : ~m);
}

// ---------------- packed fp32x2 helpers (B300 FFMA2 path, PTX-only) --------
__device__ __forceinline__ unsigned long long dup2(float a) {
    unsigned long long r;
    asm("mov.b64 %0, {%1, %1};" : "=l"(r) : "f"(a));
    return r;
}
__device__ __forceinline__ void fma2(unsigned long long& d, unsigned long long a,
                                     unsigned long long b) {
    asm("fma.rn.f32x2 %0, %1, %2, %0;" : "+l"(d) : "l"(a), "l"(b));
}
__device__ __forceinline__ float2 unpk(unsigned long long v) {
    float2 r;
    asm("mov.b64 {%0, %1}, %2;" : "=f"(r.x), "=f"(r.y) : "l"(v));
    return r;
}

// ---------------- kernel 0: zero accumulators ----------------
__global__ void k_zero() {
    int t = threadIdx.x;
    if (t < Oo) { g_sum[t] = 0.0; g_sumsq[t] = 0.0; }
}

// ---------------- kernel 1: transpose x -> xt, compute sq ----------------
__global__ void k_prep(const float* __restrict__ x) {
    int p = blockIdx.x * 256 + threadIdx.x;   // 0..16383
    int b = p >> 13;
    int n = p & (Nn - 1);
    const float* xb = x + (size_t)b * Cc * Nn;
    float s = 0.f;
    #pragma unroll
    for (int c = 0; c < Cc; c++) {
        float v = xb[c * Nn + n];
        s += v * v;
        g_xt[(size_t)p * Cc + c] = v;
    }
    g_sq[p] = s;
}

// ---------------- kernel 2: neg-dist GEMM via packed FFMA2 -----------------
// d = 2*x_i.x_j - |x_i|^2 - |x_j|^2. 128x128 tile, 256 threads, 8x8 micro.
// Accumulators paired along j: acc2[i][q] holds (acc[i][2q], acc[i][2q+1]).
// b-pairs load directly as 64-bit halves of the float4 LDS; a is dup-packed.
// Per-lane arithmetic is bitwise identical to the scalar FFMA version.
#define DSTRIDE 132
__global__ void k_dist(const float* __restrict__ x) {
    extern __shared__ float sm[];
    float* As = sm;
    float* Bs = sm + 64 * DSTRIDE;
    const int b  = blockIdx.z;
    const int i0 = blockIdx.y * 128;
    const int j0 = blockIdx.x * 128;
    const int tid = threadIdx.x;
    const float* xb = x + (size_t)b * Cc * Nn;

    for (int L = tid; L < 2048; L += 256) {
        int c = L >> 5, q = L & 31;
        float4 v = *(const float4*)(xb + c * Nn + i0 + q * 4);
        *(float4*)(As + c * DSTRIDE + q * 4) = v;
        float4 w = *(const float4*)(xb + c * Nn + j0 + q * 4);
        *(float4*)(Bs + c * DSTRIDE + q * 4) = w;
    }
    __syncthreads();

    int tx = tid & 15, ty = tid >> 4;
    unsigned long long acc2[8][4];
    #pragma unroll
    for (int i = 0; i < 8; i++)
        #pragma unroll
        for (int q = 0; q < 4; q++) acc2[i][q] = 0ull;

    #pragma unroll 4
    for (int kk = 0; kk < 64; kk++) {
        // 16B-aligned: DSTRIDE*4 = 528 = 33*16, tx*8 floats = 32B
        ulonglong2 bb0 = *(const ulonglong2*)(Bs + kk * DSTRIDE + tx * 8);
        ulonglong2 bb1 = *(const ulonglong2*)(Bs + kk * DSTRIDE + tx * 8 + 4);
        float4 a0 = *(const float4*)(As + kk * DSTRIDE + ty * 8);
        float4 a1 = *(const float4*)(As + kk * DSTRIDE + ty * 8 + 4);
        float a[8] = {a0.x, a0.y, a0.z, a0.w, a1.x, a1.y, a1.z, a1.w};
        #pragma unroll
        for (int i = 0; i < 8; i++) {
            unsigned long long ap = dup2(a[i]);
            fma2(acc2[i][0], ap, bb0.x);
            fma2(acc2[i][1], ap, bb0.y);
            fma2(acc2[i][2], ap, bb1.x);
            fma2(acc2[i][3], ap, bb1.y);
        }
    }

    float sqj[8];
    #pragma unroll
    for (int j = 0; j < 8; j++) sqj[j] = g_sq[b * Nn + j0 + tx * 8 + j];
    #pragma unroll
    for (int i = 0; i < 8; i++) {
        float sqi = g_sq[b * Nn + i0 + ty * 8 + i];
        float* dst = g_ndist + ((size_t)(b * Nn + i0 + ty * 8 + i)) * Nn + j0 + tx * 8;
        float2 p0 = unpk(acc2[i][0]);
        float2 p1 = unpk(acc2[i][1]);
        float2 p2 = unpk(acc2[i][2]);
        float2 p3 = unpk(acc2[i][3]);
        float4 r0, r1;
        r0.x = 2.f * p0.x - sqi - sqj[0];
        r0.y = 2.f * p0.y - sqi - sqj[1];
        r0.z = 2.f * p1.x - sqi - sqj[2];
        r0.w = 2.f * p1.y - sqi - sqj[3];
        r1.x = 2.f * p2.x - sqi - sqj[4];
        r1.y = 2.f * p2.y - sqi - sqj[5];
        r1.z = 2.f * p3.x - sqi - sqj[6];
        r1.w = 2.f * p3.y - sqi - sqj[7];
        *(float4*)dst = r0;
        *(float4*)(dst + 4) = r1;
    }
}

// ---------------- kernel 3: top-K set select, streaming --------------------
// Sample 256 entries straight from gmem, threshold = 12th largest sample,
// then stream the row (4xfloat4 chunks) comparing/compacting on the fly.
// Low regs -> high occupancy -> cross-block overlap keeps DRAM busy.
// Exact fallback if under/overflow (P ~ 1e-13). Tie-break = lowest index.
#define TCAP 1536
__global__ __launch_bounds__(256) void k_topk() {
    __shared__ float compv[TCAP];
    __shared__ int   compi[TCAP];
    __shared__ float samp[256];
    __shared__ float s_thr;
    __shared__ int   s_n;
    __shared__ int   chosen[Kk];

    int row  = blockIdx.x;
    int tid  = threadIdx.x;
    int lane = tid & 31;
    int warp = tid >> 5;
    const float*  srcf = g_ndist + (size_t)row * Nn;
    const float4* src  = (const float4*)srcf;

    // scattered sample (256 distinct positions)
    samp[tid] = srcf[tid * 32 + (tid & 31)];
    if (tid == 0) s_n = 0;
    __syncthreads();

    // warp 0: threshold = 12th largest of 256 samples
    if (warp == 0) {
        float lv[8];
        #pragma unroll
        for (int s = 0; s < 8; s++) lv[s] = samp[lane + 32 * s];
        for (int k = 0; ; k++) {
            float lmax = lv[0];
            #pragma unroll
            for (int s = 1; s < 8; s++) lmax = fmaxf(lmax, lv[s]);
            unsigned key = f2key(lmax);
            unsigned m = __reduce_max_sync(0xffffffffu, key);
            if (k == 11) { if (lane == 0) s_thr = key2f(m); break; }
            int win = __ffs(__ballot_sync(0xffffffffu, key == m)) - 1;
            if (lane == win) {
                bool done = false;
                #pragma unroll
                for (int s = 0; s < 8; s++)
                    if (!done && lv[s] == lmax) { lv[s] = -INFINITY; done = true; }
            }
        }
    }
    __syncthreads();
    float thr = s_thr;

    // stream + compact (two independent 4xfloat4 batches, MLP=4)
    #pragma unroll
    for (int c = 0; c < 2; c++) {
        float4 w[4];
        #pragma unroll
        for (int s = 0; s < 4; s++) w[s] = src[tid + (c * 4 + s) * 256];
        #pragma unroll
        for (int s = 0; s < 4; s++) {
            int j = (tid + (c * 4 + s) * 256) * 4;
            if (w[s].x > thr) { int p = atomicAdd(&s_n, 1); if (p < TCAP) { compv[p] = w[s].x; compi[p] = j;     } }
            if (w[s].y > thr) { int p = atomicAdd(&s_n, 1); if (p < TCAP) { compv[p] = w[s].y; compi[p] = j + 1; } }
            if (w[s].z > thr) { int p = atomicAdd(&s_n, 1); if (p < TCAP) { compv[p] = w[s].z; compi[p] = j + 2; } }
            if (w[s].w > thr) { int p = atomicAdd(&s_n, 1); if (p < TCAP) { compv[p] = w[s].w; compi[p] = j + 3; } }
        }
    }
    __syncthreads();
    int n = s_n;

    if (n >= Kk && n <= TCAP) {
        if (warp == 0) {
            int nseg = (n + 31) >> 5;
            float bv = -INFINITY; int bs = -1;
            for (int s = 0; s < nseg; s++) {
                int c = lane + (s << 5);
                if (c < n && compv[c] > bv) { bv = compv[c]; bs = c; }
            }
            for (int k = 0; k < Kk; k++) {
                unsigned key = f2key(bv);
                unsigned m = __reduce_max_sync(0xffffffffu, key);
                int cand = (key == m && bs >= 0) ? compi[bs] : 0x7fffffff;
                int widx = __reduce_min_sync(0xffffffffu, cand);
                if (lane == 0) g_idx[row * Kk + k] = widx;
                if (cand == widx) {
                    compv[bs] = -INFINITY;
                    bv = -INFINITY; bs = -1;
                    for (int s = 0; s < nseg; s++) {
                        int c = lane + (s << 5);
                        if (c < n && compv[c] > bv) { bv = compv[c]; bs = c; }
                    }
                }
            }
        }
    } else if (warp == 0) {
        // exact fallback: 20 passes over the global row (never runs in practice)
        for (int k = 0; k < Kk; k++) {
            float bv = -INFINITY; int bi = 0x7fffffff;
            for (int j = lane; j < Nn; j += 32) {
                bool skip = false;
                for (int q = 0; q < k; q++) if (chosen[q] == j) skip = true;
                float val = srcf[j];
                if (!skip && val > bv) { bv = val; bi = j; }
            }
            unsigned key = f2key(bv);
            unsigned m = __reduce_max_sync(0xffffffffu, key);
            int cand = (key == m) ? bi : 0x7fffffff;
            int widx = __reduce_min_sync(0xffffffffu, cand);
            if (lane == 0) { g_idx[row * Kk + k] = widx; chosen[k] = widx; }
            __syncwarp();
        }
    }
}

// ---------------- kernel 4: center term u = (W[:,C:]-W[:,:C]) . cen -------
__global__ void k_u(const float* __restrict__ W) {
    __shared__ float Wd[64 * 65];   // [c][o], stride 65 (conflict-free)
    __shared__ float cs[4 * 64];
    int tid = threadIdx.x;
    for (int L = tid; L < 4096; L += 256) {
        int c = L & 63, o = L >> 6;
        Wd[c * 65 + o] = W[o * 128 + 64 + c] - W[o * 128 + c];
    }
    int p0 = blockIdx.x * 4;
    {
        int pi = tid >> 6, c = tid & 63;
        cs[pi * 64 + c] = g_xt[(size_t)(p0 + pi) * 64 + c];
    }
    __syncthreads();
    int o = tid & 63, pi = tid >> 6;
    float a = 0.f;
    #pragma unroll
    for (int c = 0; c < 64; c++) a += Wd[c * 65 + o] * cs[pi * 64 + c];
    g_u[(size_t)(p0 + pi) * 64 + o] = a;
}

// ---------------- kernel 5/7: gathered GEMM  h = A·nbr + u ----------------
#define SA 161
#define WS_OFF 10400   // floats (41600 B region for As/hbuf)
template<int MODE>
__global__ void k_conv(const float* __restrict__ W, float* __restrict__ out) {
    extern __shared__ float sm[];
    float* As = sm;            // [64][161]  (MODE1: reused as hbuf [160][65])
    float* Ws = sm + WS_OFF;   // [64][68]
    __shared__ int   rowb[160];
    __shared__ int   ub[160];
    __shared__ float ssum[64];
    __shared__ float ssq[64];
    __shared__ float ssc[64];
    __shared__ float ssh[64];

    int tid = threadIdx.x;
    int m0 = blockIdx.x * 160;

    if (tid < 160) {
        int m = m0 + tid;
        int nb = g_idx[m];
        int pt = m / Kk;           // global point index b*N+n
        int b  = pt >> 13;
        rowb[tid] = b * Nn + nb;   // gathered xt row
        ub[tid]   = pt;            // u row
    }
    for (int L = tid; L < 4096; L += 256) {
        int c = L & 63, o = L >> 6;
        Ws[c * 68 + o] = W[o * 128 + c];   // A part, K-major
    }
    if (MODE == 0) { if (tid < 64) { ssum[tid] = 0.f; ssq[tid] = 0.f; } }
    else           { if (tid < 64) { ssc[tid] = g_sc[tid]; ssh[tid] = g_sh[tid]; } }
    __syncthreads();

    for (int L = tid; L < 2560; L += 256) {
        int r = L >> 4, c4 = L & 15;
        float4 v = *(const float4*)(g_xt + (size_t)rowb[r] * 64 + c4 * 4);
        As[(c4 * 4 + 0) * SA + r] = v.x;
        As[(c4 * 4 + 1) * SA + r] = v.y;
        As[(c4 * 4 + 2) * SA + r] = v.z;
        As[(c4 * 4 + 3) * SA + r] = v.w;
    }
    __syncthreads();

    int tx = tid & 7, ty = tid >> 3;   // tx: 8 col-groups, ty: 32 row-groups
    float acc[5][8];
    #pragma unroll
    for (int i = 0; i < 5; i++)
        #pragma unroll
        for (int j = 0; j < 8; j++) acc[i][j] = 0.f;

    #pragma unroll 4
    for (int kk = 0; kk < 64; kk++) {
        float a[5];
        #pragma unroll
        for (int i = 0; i < 5; i++) a[i] = As[kk * SA + ty * 5 + i];
        float4 b0 = *(float4*)(Ws + kk * 68 + tx * 8);
        float4 b1 = *(float4*)(Ws + kk * 68 + tx * 8 + 4);
        float bbv[8] = {b0.x, b0.y, b0.z, b0.w, b1.x, b1.y, b1.z, b1.w};
        #pragma unroll
        for (int i = 0; i < 5; i++)
            #pragma unroll
            for (int j = 0; j < 8; j++) acc[i][j] += a[i] * bbv[j];
    }

    // add center term
    float hv[5][8];
    #pragma unroll
    for (int i = 0; i < 5; i++) {
        const float* up = g_u + (size_t)ub[ty * 5 + i] * 64 + tx * 8;
        float4 u0 = *(const float4*)up;
        float4 u1 = *(const float4*)(up + 4);
        float uv[8] = {u0.x, u0.y, u0.z, u0.w, u1.x, u1.y, u1.z, u1.w};
        #pragma unroll
        for (int j = 0; j < 8; j++) hv[i][j] = acc[i][j] + uv[j];
    }

    if (MODE == 0) {
        float ps[8], pq[8];
        #pragma unroll
        for (int j = 0; j < 8; j++) { ps[j] = 0.f; pq[j] = 0.f; }
        #pragma unroll
        for (int i = 0; i < 5; i++)
            #pragma unroll
            for (int j = 0; j < 8; j++) {
                float v = hv[i][j];
                ps[j] += v; pq[j] += v * v;
            }
        #pragma unroll
        for (int j = 0; j < 8; j++) {
            atomicAdd(&ssum[tx * 8 + j], ps[j]);
            atomicAdd(&ssq [tx * 8 + j], pq[j]);
        }
        __syncthreads();
        if (tid < 64) {
            atomicAdd(&g_sum[tid],   (double)ssum[tid]);
            atomicAdd(&g_sumsq[tid], (double)ssq[tid]);
        }
    } else {
        __syncthreads();  // As fully consumed; safe to reuse as hbuf
        #pragma unroll
        for (int i = 0; i < 5; i++)
            #pragma unroll
            for (int j = 0; j < 8; j++) {
                int o = tx * 8 + j;
                float v = hv[i][j] * ssc[o] + ssh[o];
                v = (v >= 0.f) ? v : 0.2f * v;
                As[(ty * 5 + i) * 65 + o] = v;
            }
        __syncthreads();
        for (int task = tid; task < 512; task += 256) {
            int p = task >> 6, o = task & 63;
            float mx = -INFINITY;
            #pragma unroll
            for (int k = 0; k < Kk; k++)
                mx = fmaxf(mx, As[(p * Kk + k) * 65 + o]);
            int pt = m0 / Kk + p;
            int b = pt >> 13, n = pt & (Nn - 1);
            out[((size_t)b * 64 + o) * Nn + n] = mx;
        }
    }
}

// ---------------- kernel 6: finalize BN scale/shift ----------------
__global__ void k_fin(const float* __restrict__ gamma, const float* __restrict__ beta) {
    int o = threadIdx.x;
    if (o < Oo) {
        double cnt  = (double)MROWS;
        double mean = g_sum[o] / cnt;
        double var  = g_sumsq[o] / cnt - mean * mean;
        float inv = rsqrtf((float)(var + 1e-5));
        float sc  = gamma[o] * inv;
        g_sc[o] = sc;
        g_sh[o] = beta[o] - (float)mean * sc;
    }
}

// ---------------- launcher ----------------
extern "C" void kernel_launch(void* const* d_in, const int* in_sizes, int n_in,
                              void* d_out, int out_size) {
    const float* x     = (const float*)d_in[0];
    const float* W     = (const float*)d_in[1];
    const float* gamma = (const float*)d_in[2];
    const float* beta  = (const float*)d_in[3];
    float* out = (float*)d_out;

    const int SMEM_DIST = 2 * 64 * DSTRIDE * sizeof(float);          // 67584
    const int SMEM_CONV = (WS_OFF + 64 * 68) * sizeof(float);        // 59008

    cudaFuncSetAttribute(k_dist,    cudaFuncAttributeMaxDynamicSharedMemorySize, SMEM_DIST);
    cudaFuncSetAttribute(k_conv<0>, cudaFuncAttributeMaxDynamicSharedMemorySize, SMEM_CONV);
    cudaFuncSetAttribute(k_conv<1>, cudaFuncAttributeMaxDynamicSharedMemorySize, SMEM_CONV);

    k_zero<<<1, 64>>>();
    k_prep<<<NPOINTS / 256, 256>>>(x);
    k_dist<<<dim3(Nn / 128, Nn / 128, Bb), 256, SMEM_DIST>>>(x);
    k_topk<<<NPOINTS, 256>>>();
    k_u<<<NPOINTS / 4, 256>>>(W);
    k_conv<0><<<NBLK_CONV, 256, SMEM_CONV>>>(W, out);
    k_fin<<<1, 64>>>(gamma, beta);
    k_conv<1><<<NBLK_CONV, 256, SMEM_CONV>>>(W, out);
}